// round 8
// baseline (speedup 1.0000x reference)
#include <cuda_runtime.h>
#include <cuda_bf16.h>
#include <math.h>
#include <stdint.h>

// ---------------------------------------------------------------------------
// BSPLoss: out = lam1 + 0.5*(lam2+lam3), lam_i = top eigenvalue of F_i^T F_i.
// Gram (4-way K-split) + 10 Frobenius-normalized symmetric squarings.
// Squarings: CTA tile 256x128 (8 warps of 64x64), K-split 2; the two k-half
// CTAs merge via a second-arriver protocol INSIDE the kernel (no merge
// launch).  All GEMMs mma.sync.m16n8k16 bf16 hi/lo split, fp32 accum.
// ---------------------------------------------------------------------------

#define DIM    1024
#define NROWS  8192
#define M_SQ   10
#define NTILE  36
#define KSPLIT 4

// Gram kernel (KC=16, 128 threads) -- proven config
#define KCG     16
#define GREGB   4096
#define GSTAGEB (4 * GREGB)
#define GSMEMB  (2 * GSTAGEB + 1024)

// Squaring kernel: tile 256x128, KC=16, double buffered
#define QTILES  20
#define KCQ     16
#define IREGB   8192
#define JREGB   4096
#define QSTAGEB (2 * IREGB + 2 * JREGB)   // 24 KB
#define QSMEM   (2 * QSTAGEB)             // 48 KB

__device__ __align__(16) float g_bufA[3][DIM * DIM];
__device__ __align__(16) float g_bufB[3][DIM * DIM];
__device__ __align__(16) float g_part[KSPLIT][3][DIM * DIM];
__device__ double g_frob[3];
__device__ float  g_inv[3];
__device__ double g_logacc[3];
__device__ int    g_ctr[3];
__device__ int    g_tctr[3][QTILES];

__global__ void init_kernel() {
    int i = threadIdx.x;
    if (i < 3) { g_frob[i] = 0.0; g_inv[i] = 1.0f; g_logacc[i] = 0.0; g_ctr[i] = 0; }
    if (i < 3 * QTILES) g_tctr[i / QTILES][i % QTILES] = 0;
}

__device__ __forceinline__ uint32_t smem_u32(const void* p) {
    uint32_t a;
    asm("{ .reg .u64 t; cvta.to.shared.u64 t, %1; cvt.u32.u64 %0, t; }"
        : "=r"(a) : "l"(p));
    return a;
}

__device__ __forceinline__ void ldsm4t(uint32_t* r, uint32_t addr) {
    asm volatile("ldmatrix.sync.aligned.m8n8.x4.trans.shared.b16 {%0,%1,%2,%3}, [%4];"
                 : "=r"(r[0]), "=r"(r[1]), "=r"(r[2]), "=r"(r[3]) : "r"(addr));
}

__device__ __forceinline__ void mma16816(float* c, const uint32_t* a,
                                         uint32_t b0, uint32_t b1) {
    asm volatile("mma.sync.aligned.m16n8k16.row.col.f32.bf16.bf16.f32 "
                 "{%0,%1,%2,%3}, {%4,%5,%6,%7}, {%8,%9}, {%0,%1,%2,%3};"
                 : "+f"(c[0]), "+f"(c[1]), "+f"(c[2]), "+f"(c[3])
                 : "r"(a[0]), "r"(a[1]), "r"(a[2]), "r"(a[3]), "r"(b0), "r"(b1));
}

__device__ __forceinline__ uint32_t swz256(uint32_t base, int row, int chunk) {
    return base + row * 256 + ((chunk ^ (row & 7)) << 4);
}

__device__ __forceinline__ float2 ldcg2(const float* p) {
    float2 v;
    asm volatile("ld.global.cg.v2.f32 {%0, %1}, [%2];"
                 : "=f"(v.x), "=f"(v.y) : "l"(p));
    return v;
}

__device__ __forceinline__ void cvt_hl(float4 v, uint2& hi, uint2& lo) {
    __nv_bfloat162 h0 = __floats2bfloat162_rn(v.x, v.y);
    __nv_bfloat162 h1 = __floats2bfloat162_rn(v.z, v.w);
    __nv_bfloat162 l0 = __floats2bfloat162_rn(v.x - __bfloat162float(h0.x),
                                              v.y - __bfloat162float(h0.y));
    __nv_bfloat162 l1 = __floats2bfloat162_rn(v.z - __bfloat162float(h1.x),
                                              v.w - __bfloat162float(h1.y));
    hi.x = *(uint32_t*)&h0; hi.y = *(uint32_t*)&h1;
    lo.x = *(uint32_t*)&l0; lo.y = *(uint32_t*)&l1;
}

// ============ Gram kernel (proven): 128 thr, KC=16, K-split grid ============
__device__ __forceinline__ void gram_store_stage(char* bufp, const float4* rI,
                                                 const float4* rJ, int row, int c4) {
#pragma unroll
    for (int it = 0; it < 4; it++) {
        const int col4 = c4 + it * 8;
        const int chunk = col4 >> 1;
        const uint32_t off = (uint32_t)(row * 256) +
                             ((chunk ^ (row & 7)) << 4) + ((col4 & 1) * 8);
        uint2 hi, lo;
        cvt_hl(rI[it], hi, lo);
        *(uint2*)(bufp + off)         = hi;
        *(uint2*)(bufp + GREGB + off) = lo;
        cvt_hl(rJ[it], hi, lo);
        *(uint2*)(bufp + 2 * GREGB + off) = hi;
        *(uint2*)(bufp + 3 * GREGB + off) = lo;
    }
}

__device__ __forceinline__ void gram_compute(uint32_t u, float acc[4][8][4],
                                             int wm, int wn, int g, int tr) {
    const uint32_t IHI = u, ILO = u + GREGB, JHI = u + 2 * GREGB, JLO = u + 3 * GREGB;
    const int rowA = ((g & 2) ? 8 : 0) + tr;
    const int rowB = ((g & 1) ? 8 : 0) + tr;
    uint32_t ax[4][4], bh[4][4], bx[4][4];
#pragma unroll
    for (int mi = 0; mi < 4; mi++)
        ldsm4t(ax[mi], swz256(IHI, rowA, (wm >> 3) + mi * 2 + (g & 1)));
#pragma unroll
    for (int nb = 0; nb < 4; nb++)
        ldsm4t(bh[nb], swz256(JHI, rowB, (wn >> 3) + nb * 2 + (g >> 1)));
#pragma unroll
    for (int mi = 0; mi < 4; mi++)
#pragma unroll
        for (int nj = 0; nj < 8; nj++)
            mma16816(acc[mi][nj], ax[mi],
                     bh[nj >> 1][(nj & 1) * 2], bh[nj >> 1][(nj & 1) * 2 + 1]);
#pragma unroll
    for (int nb = 0; nb < 4; nb++)
        ldsm4t(bx[nb], swz256(JLO, rowB, (wn >> 3) + nb * 2 + (g >> 1)));
#pragma unroll
    for (int mi = 0; mi < 4; mi++)
#pragma unroll
        for (int nj = 0; nj < 8; nj++)
            mma16816(acc[mi][nj], ax[mi],
                     bx[nj >> 1][(nj & 1) * 2], bx[nj >> 1][(nj & 1) * 2 + 1]);
#pragma unroll
    for (int mi = 0; mi < 4; mi++)
        ldsm4t(ax[mi], swz256(ILO, rowA, (wm >> 3) + mi * 2 + (g & 1)));
#pragma unroll
    for (int mi = 0; mi < 4; mi++)
#pragma unroll
        for (int nj = 0; nj < 8; nj++)
            mma16816(acc[mi][nj], ax[mi],
                     bh[nj >> 1][(nj & 1) * 2], bh[nj >> 1][(nj & 1) * 2 + 1]);
}

__global__ void __launch_bounds__(128)
ata_mma_kernel(const float* __restrict__ a0, const float* __restrict__ a1,
               const float* __restrict__ a2, int Kper)
{
    extern __shared__ __align__(16) char dynsmem[];

    const int z = blockIdx.z;
    const float* A = (z == 0) ? a0 : ((z == 1) ? a1 : a2);
    float* C = g_part[blockIdx.y][z];

    int t = blockIdx.x, bi = 0;
    while (t >= 8 - bi) { t -= 8 - bi; bi++; }
    const int bj = bi + t;
    const int i0 = bi * 128, j0 = bj * 128;

    const int tid = threadIdx.x;
    const int w = tid >> 5, l = tid & 31;
    const int wm = (w >> 1) * 64, wn = (w & 1) * 64;
    const int tr = l & 7, g = l >> 3;
    const int row = tid >> 3, c4 = tid & 7;

    const uint32_t sb = smem_u32(dynsmem);
    const uint32_t ab = (sb + 1023u) & ~1023u;
    char* aptr = dynsmem + (ab - sb);

    float acc[4][8][4];
#pragma unroll
    for (int mi = 0; mi < 4; mi++)
#pragma unroll
        for (int nj = 0; nj < 8; nj++)
#pragma unroll
            for (int q = 0; q < 4; q++) acc[mi][nj][q] = 0.0f;

    const size_t kbase = (size_t)blockIdx.y * Kper;
    const float* pI = A + kbase * DIM + i0 + c4 * 4;
    const float* pJ = A + kbase * DIM + j0 + c4 * 4;

    const int S = Kper / KCG;
    float4 rI[4], rJ[4];
    {
        const size_t b0 = (size_t)row * DIM;
#pragma unroll
        for (int it = 0; it < 4; it++) {
            rI[it] = *(const float4*)(pI + b0 + it * 32);
            rJ[it] = *(const float4*)(pJ + b0 + it * 32);
        }
    }
    gram_store_stage(aptr, rI, rJ, row, c4);
    {
        const size_t b1 = (size_t)(KCG + row) * DIM;
#pragma unroll
        for (int it = 0; it < 4; it++) {
            rI[it] = *(const float4*)(pI + b1 + it * 32);
            rJ[it] = *(const float4*)(pJ + b1 + it * 32);
        }
    }
    __syncthreads();

    for (int s = 0; s < S; s++) {
        const int b = s & 1;
        if (s + 1 < S)
            gram_store_stage(aptr + (b ^ 1) * GSTAGEB, rI, rJ, row, c4);
        if (s + 2 < S) {
            const size_t bb = (size_t)((s + 2) * KCG + row) * DIM;
#pragma unroll
            for (int it = 0; it < 4; it++) {
                rI[it] = *(const float4*)(pI + bb + it * 32);
                rJ[it] = *(const float4*)(pJ + bb + it * 32);
            }
        }
        gram_compute(ab + b * GSTAGEB, acc, wm, wn, g, tr);
        __syncthreads();
    }

    const int r  = l >> 2;
    const int c2 = 2 * (l & 3);
#pragma unroll
    for (int mi = 0; mi < 4; mi++) {
#pragma unroll
        for (int nj = 0; nj < 8; nj++) {
            float* a = acc[mi][nj];
            const int gr = i0 + wm + mi * 16 + r;
            const int gc = j0 + wn + nj * 8 + c2;
            *(float2*)&C[(size_t)gr * DIM + gc]       = make_float2(a[0], a[1]);
            *(float2*)&C[(size_t)(gr + 8) * DIM + gc] = make_float2(a[2], a[3]);
            if (bi != bj) {
                C[(size_t)gc * DIM + gr]           = a[0];
                C[(size_t)(gc + 1) * DIM + gr]     = a[1];
                C[(size_t)gc * DIM + gr + 8]       = a[2];
                C[(size_t)(gc + 1) * DIM + gr + 8] = a[3];
            }
        }
    }
}

__global__ void add_parts_kernel() {
    const int z = blockIdx.y;
    float4* d        = reinterpret_cast<float4*>(g_bufA[z]);
    const float4* p0 = reinterpret_cast<const float4*>(g_part[0][z]);
    const float4* p1 = reinterpret_cast<const float4*>(g_part[1][z]);
    const float4* p2 = reinterpret_cast<const float4*>(g_part[2][z]);
    const float4* p3 = reinterpret_cast<const float4*>(g_part[3][z]);
    const int n = DIM * DIM / 4;
    for (int i = blockIdx.x * blockDim.x + threadIdx.x; i < n;
         i += gridDim.x * blockDim.x) {
        float4 a = p0[i], b = p1[i], c = p2[i], e = p3[i];
        float4 o;
        o.x = (a.x + b.x) + (c.x + e.x);
        o.y = (a.y + b.y) + (c.y + e.y);
        o.z = (a.z + b.z) + (c.z + e.z);
        o.w = (a.w + b.w) + (c.w + e.w);
        d[i] = o;
    }
}

// ============ Squaring kernel: fused K-split merge (second arriver) =========
__global__ void __launch_bounds__(256, 1)
sq2_mma_kernel(int src_sel, int dst_sel, int do_write, double wfin)
{
    extern __shared__ __align__(16) char dynsmem[];
    __shared__ float sh_wsum[8];
    __shared__ int sh_rank;

    const int z  = blockIdx.z;
    const int ky = blockIdx.y;          // k-half: 0 or 1
    const float* A = (src_sel == 1) ? g_bufA[z] : g_bufB[z];
    float* C       = (dst_sel == 1) ? g_bufA[z] : g_bufB[z];

    int t = blockIdx.x, bi = 0;
    while (t >= 8 - 2 * bi) { t -= 8 - 2 * bi; bi++; }
    const int bj = 2 * bi + t;
    const int i0 = bi * 256, j0 = bj * 128;

    const int tid = threadIdx.x;
    const int w = tid >> 5, l = tid & 31;
    const int wm = (w >> 1) * 64, wn = (w & 1) * 64;
    const int tr = l & 7, g = l >> 3;
    const int trow = tid >> 4, tc = tid & 15;

    const float sv = g_inv[z];
    const float s2 = sv * sv;

    const uint32_t sb = smem_u32(dynsmem);
    char* aptr = dynsmem;

    float acc[4][8][4];
#pragma unroll
    for (int mi = 0; mi < 4; mi++)
#pragma unroll
        for (int nj = 0; nj < 8; nj++)
#pragma unroll
            for (int q = 0; q < 4; q++) acc[mi][nj][q] = 0.0f;

    const size_t kbase = (size_t)ky * (DIM / 2);
    const float* pI = A + kbase * DIM + i0 + tc * 4;
    const float* pJ = A + kbase * DIM + j0 + tc * 4;

    const int S = (DIM / 2) / KCQ;
    float4 rI[4], rJ[2];

    {
        const size_t b0 = (size_t)trow * DIM;
#pragma unroll
        for (int it = 0; it < 4; it++) rI[it] = *(const float4*)(pI + b0 + it * 64);
#pragma unroll
        for (int it = 0; it < 2; it++) rJ[it] = *(const float4*)(pJ + b0 + it * 64);
    }
    {
        char* bufp = aptr;
#pragma unroll
        for (int it = 0; it < 4; it++) {
            const int col4 = tc + it * 16;
            const int chunk = col4 >> 1;
            const uint32_t offx = (uint32_t)(trow * 512) +
                (((chunk & 0x18) | ((chunk ^ (trow & 7)) & 7)) << 4) + ((col4 & 1) * 8);
            uint2 hi, lo;
            cvt_hl(rI[it], hi, lo);
            *(uint2*)(bufp + offx)         = hi;
            *(uint2*)(bufp + IREGB + offx) = lo;
        }
#pragma unroll
        for (int it = 0; it < 2; it++) {
            const int col4 = tc + it * 16;
            const int chunk = col4 >> 1;
            const uint32_t off = (uint32_t)(trow * 256) +
                                 ((chunk ^ (trow & 7)) << 4) + ((col4 & 1) * 8);
            uint2 hi, lo;
            cvt_hl(rJ[it], hi, lo);
            *(uint2*)(bufp + 2 * IREGB + off)         = hi;
            *(uint2*)(bufp + 2 * IREGB + JREGB + off) = lo;
        }
    }
    {
        const size_t b1 = (size_t)(KCQ + trow) * DIM;
#pragma unroll
        for (int it = 0; it < 4; it++) rI[it] = *(const float4*)(pI + b1 + it * 64);
#pragma unroll
        for (int it = 0; it < 2; it++) rJ[it] = *(const float4*)(pJ + b1 + it * 64);
    }
    __syncthreads();

    for (int s = 0; s < S; s++) {
        const int b = s & 1;
        if (s + 1 < S) {
            char* bufp = aptr + (b ^ 1) * QSTAGEB;
#pragma unroll
            for (int it = 0; it < 4; it++) {
                const int col4 = tc + it * 16;
                const int chunk = col4 >> 1;
                const uint32_t offx = (uint32_t)(trow * 512) +
                    (((chunk & 0x18) | ((chunk ^ (trow & 7)) & 7)) << 4) +
                    ((col4 & 1) * 8);
                uint2 hi, lo;
                cvt_hl(rI[it], hi, lo);
                *(uint2*)(bufp + offx)         = hi;
                *(uint2*)(bufp + IREGB + offx) = lo;
            }
#pragma unroll
            for (int it = 0; it < 2; it++) {
                const int col4 = tc + it * 16;
                const int chunk = col4 >> 1;
                const uint32_t off = (uint32_t)(trow * 256) +
                                     ((chunk ^ (trow & 7)) << 4) + ((col4 & 1) * 8);
                uint2 hi, lo;
                cvt_hl(rJ[it], hi, lo);
                *(uint2*)(bufp + 2 * IREGB + off)         = hi;
                *(uint2*)(bufp + 2 * IREGB + JREGB + off) = lo;
            }
        }
        if (s + 2 < S) {
            const size_t bb = (size_t)((s + 2) * KCQ + trow) * DIM;
#pragma unroll
            for (int it = 0; it < 4; it++) rI[it] = *(const float4*)(pI + bb + it * 64);
#pragma unroll
            for (int it = 0; it < 2; it++) rJ[it] = *(const float4*)(pJ + bb + it * 64);
        }
        {
            const uint32_t u = sb + b * QSTAGEB;
            const uint32_t IHI = u, ILO = u + IREGB;
            const uint32_t JHI = u + 2 * IREGB, JLO = u + 2 * IREGB + JREGB;
            const int rowA = ((g & 2) ? 8 : 0) + tr;
            const int rowB = ((g & 1) ? 8 : 0) + tr;
            uint32_t ax[4][4], bh[4][4], bx[4][4];
#pragma unroll
            for (int mi = 0; mi < 4; mi++) {
                const int ch = (wm >> 3) + mi * 2 + (g & 1);
                const uint32_t ad = IHI + rowA * 512 +
                    (((ch & 0x18) | ((ch ^ (rowA & 7)) & 7)) << 4);
                ldsm4t(ax[mi], ad);
            }
#pragma unroll
            for (int nb = 0; nb < 4; nb++)
                ldsm4t(bh[nb], swz256(JHI, rowB, (wn >> 3) + nb * 2 + (g >> 1)));
#pragma unroll
            for (int mi = 0; mi < 4; mi++)
#pragma unroll
                for (int nj = 0; nj < 8; nj++)
                    mma16816(acc[mi][nj], ax[mi],
                             bh[nj >> 1][(nj & 1) * 2], bh[nj >> 1][(nj & 1) * 2 + 1]);
#pragma unroll
            for (int nb = 0; nb < 4; nb++)
                ldsm4t(bx[nb], swz256(JLO, rowB, (wn >> 3) + nb * 2 + (g >> 1)));
#pragma unroll
            for (int mi = 0; mi < 4; mi++)
#pragma unroll
                for (int nj = 0; nj < 8; nj++)
                    mma16816(acc[mi][nj], ax[mi],
                             bx[nj >> 1][(nj & 1) * 2], bx[nj >> 1][(nj & 1) * 2 + 1]);
#pragma unroll
            for (int mi = 0; mi < 4; mi++) {
                const int ch = (wm >> 3) + mi * 2 + (g & 1);
                const uint32_t ad = ILO + rowA * 512 +
                    (((ch & 0x18) | ((ch ^ (rowA & 7)) & 7)) << 4);
                ldsm4t(ax[mi], ad);
            }
#pragma unroll
            for (int mi = 0; mi < 4; mi++)
#pragma unroll
                for (int nj = 0; nj < 8; nj++)
                    mma16816(acc[mi][nj], ax[mi],
                             bh[nj >> 1][(nj & 1) * 2], bh[nj >> 1][(nj & 1) * 2 + 1]);
        }
        __syncthreads();
    }

    // ---- write raw partial (direct only) ----
    const int r  = l >> 2;
    const int c2 = 2 * (l & 3);
    {
        float* P = g_part[ky][z];
#pragma unroll
        for (int mi = 0; mi < 4; mi++) {
#pragma unroll
            for (int nj = 0; nj < 8; nj++) {
                const float* a = acc[mi][nj];
                const int gr = i0 + wm + mi * 16 + r;
                const int gc = j0 + wn + nj * 8 + c2;
                *(float2*)&P[(size_t)gr * DIM + gc]       = make_float2(a[0], a[1]);
                *(float2*)&P[(size_t)(gr + 8) * DIM + gc] = make_float2(a[2], a[3]);
            }
        }
    }
    __threadfence();
    __syncthreads();
    if (tid == 0) sh_rank = atomicAdd(&g_tctr[z][blockIdx.x], 1);
    __syncthreads();
    if (sh_rank == 0) return;          // first arriver done
    if (tid == 0) g_tctr[z][blockIdx.x] = 0;
    __threadfence();

    // ---- second arriver: merge, scale, frob, store ----
    const float* Q = g_part[1 - ky][z];
    float fr = 0.0f;
#pragma unroll
    for (int mi = 0; mi < 4; mi++) {
#pragma unroll
        for (int nj = 0; nj < 8; nj++) {
            float* a = acc[mi][nj];
            const int gr = i0 + wm + mi * 16 + r;
            const int gc = j0 + wn + nj * 8 + c2;
            float2 q0 = ldcg2(&Q[(size_t)gr * DIM + gc]);
            float2 q1 = ldcg2(&Q[(size_t)(gr + 8) * DIM + gc]);
            a[0] = (a[0] + q0.x) * s2;
            a[1] = (a[1] + q0.y) * s2;
            a[2] = (a[2] + q1.x) * s2;
            a[3] = (a[3] + q1.y) * s2;
            // weights: mirror cell (gc', gr') computed by another tile?
            const int rr[4] = {gr, gr, gr + 8, gr + 8};
            const int cc[4] = {gc, gc + 1, gc, gc + 1};
#pragma unroll
            for (int q = 0; q < 4; q++) {
                const bool diag = (rr[q] == cc[q]);
                const bool cov  = ((rr[q] >> 7) >= ((cc[q] >> 8) << 1));
                const float wq  = diag ? 1.0f : (cov ? 1.0f : 2.0f);
                fr = fmaf(wq * a[q], a[q], fr);
            }
            if (do_write) {
                *(float2*)&C[(size_t)gr * DIM + gc]       = make_float2(a[0], a[1]);
                *(float2*)&C[(size_t)(gr + 8) * DIM + gc] = make_float2(a[2], a[3]);
#pragma unroll
                for (int q = 0; q < 4; q++) {
                    const bool diag = (rr[q] == cc[q]);
                    const bool cov  = ((rr[q] >> 7) >= ((cc[q] >> 8) << 1));
                    if (!diag && !cov)
                        C[(size_t)cc[q] * DIM + rr[q]] = a[q];
                }
            }
        }
    }

#pragma unroll
    for (int o = 16; o > 0; o >>= 1)
        fr += __shfl_xor_sync(0xffffffffu, fr, o);
    if (l == 0) sh_wsum[w] = fr;
    __syncthreads();
    if (tid == 0) {
        double tot = 0.0;
        for (int i = 0; i < 8; i++) tot += (double)sh_wsum[i];
        atomicAdd(&g_frob[z], tot);
        __threadfence();
        int tk = atomicAdd(&g_ctr[z], 1);
        if (tk == QTILES - 1) {
            g_ctr[z] = 0;
            __threadfence();
            double c = sqrt(g_frob[z]);
            g_inv[z] = (float)(1.0 / c);
            g_logacc[z] += log2(c) * wfin;
            g_frob[z] = 0.0;
        }
    }
}

__global__ void out_kernel(float* __restrict__ out) {
    double l0 = exp2(g_logacc[0]);
    double l1 = exp2(g_logacc[1]);
    double l2 = exp2(g_logacc[2]);
    out[0] = (float)(l0 + 0.5 * (l1 + l2));
}

extern "C" void kernel_launch(void* const* d_in, const int* in_sizes, int n_in,
                              void* d_out, int out_size)
{
    const float* f1 = (const float*)d_in[0];
    const float* f2 = (const float*)d_in[1];
    const float* f3 = (const float*)d_in[2];
    (void)in_sizes; (void)n_in; (void)out_size;

    static int configured = 0;
    if (!configured) {
        cudaFuncSetAttribute(ata_mma_kernel,
                             cudaFuncAttributeMaxDynamicSharedMemorySize, GSMEMB);
        cudaFuncSetAttribute(sq2_mma_kernel,
                             cudaFuncAttributeMaxDynamicSharedMemorySize, QSMEM);
        configured = 1;
    }

    init_kernel<<<1, 64>>>();

    // Gram: 4-way K-split into partials, sum into bufA
    ata_mma_kernel<<<dim3(NTILE, KSPLIT, 3), 128, GSMEMB>>>(
        f1, f2, f3, NROWS / KSPLIT);
    add_parts_kernel<<<dim3(128, 3), 256>>>();

    int cur = 1;
    for (int k = 1; k <= M_SQ; k++) {
        int dst = 3 - cur;
        sq2_mma_kernel<<<dim3(QTILES, 2, 3), 256, QSMEM>>>(
            cur, dst, (k < M_SQ) ? 1 : 0, exp2(-(double)k));
        cur = dst;
    }
    out_kernel<<<1, 1>>>((float*)d_out);
}

// round 9
// speedup vs baseline: 1.4218x; 1.4218x over previous
#include <cuda_runtime.h>
#include <cuda_bf16.h>
#include <math.h>
#include <stdint.h>

// ---------------------------------------------------------------------------
// BSPLoss: out = lam1 + 0.5*(lam2+lam3), lam_i = top eigenvalue of F_i^T F_i.
// Gram (4-way K-split, proven R5) + 10 Frobenius-normalized symmetric
// squarings (proven R4 kernel, templated precision: 3-product bf16 hi/lo for
// k<=2, single-product bf16 for k>=3 -- error attenuated by 2^-k weights).
// ---------------------------------------------------------------------------

#define DIM    1024
#define NROWS  8192
#define M_SQ   10
#define NTILE  36
#define KSPLIT 4

// Gram kernel (KC=16, 128 threads) -- proven config
#define KCG     16
#define GREGB   4096
#define GSTAGEB (4 * GREGB)
#define GSMEMB  (2 * GSTAGEB + 1024)

// Squaring kernel (KC=32, 256 threads, tile 128x128, warps 64x32) -- proven R4
#define KCS     32
#define SREGB   (KCS * 256)          // 8 KB
#define SSTAGEB (4 * SREGB)          // 32 KB
#define SSMEMB  (2 * SSTAGEB + 1024)

__device__ __align__(16) float g_bufA[3][DIM * DIM];
__device__ __align__(16) float g_bufB[3][DIM * DIM];
__device__ __align__(16) float g_part[KSPLIT][3][DIM * DIM];
__device__ double g_frob[3];
__device__ float  g_inv[3];
__device__ double g_logacc[3];
__device__ int    g_ctr[3];

__global__ void init_kernel() {
    int i = threadIdx.x;
    if (i < 3) { g_frob[i] = 0.0; g_inv[i] = 1.0f; g_logacc[i] = 0.0; g_ctr[i] = 0; }
}

__device__ __forceinline__ uint32_t smem_u32(const void* p) {
    uint32_t a;
    asm("{ .reg .u64 t; cvta.to.shared.u64 t, %1; cvt.u32.u64 %0, t; }"
        : "=r"(a) : "l"(p));
    return a;
}

__device__ __forceinline__ void ldsm4t(uint32_t* r, uint32_t addr) {
    asm volatile("ldmatrix.sync.aligned.m8n8.x4.trans.shared.b16 {%0,%1,%2,%3}, [%4];"
                 : "=r"(r[0]), "=r"(r[1]), "=r"(r[2]), "=r"(r[3]) : "r"(addr));
}

__device__ __forceinline__ void mma16816(float* c, const uint32_t* a,
                                         uint32_t b0, uint32_t b1) {
    asm volatile("mma.sync.aligned.m16n8k16.row.col.f32.bf16.bf16.f32 "
                 "{%0,%1,%2,%3}, {%4,%5,%6,%7}, {%8,%9}, {%0,%1,%2,%3};"
                 : "+f"(c[0]), "+f"(c[1]), "+f"(c[2]), "+f"(c[3])
                 : "r"(a[0]), "r"(a[1]), "r"(a[2]), "r"(a[3]), "r"(b0), "r"(b1));
}

__device__ __forceinline__ uint32_t swz256(uint32_t base, int row, int chunk) {
    return base + row * 256 + ((chunk ^ (row & 7)) << 4);
}

__device__ __forceinline__ void cvt_hl(float4 v, uint2& hi, uint2& lo) {
    __nv_bfloat162 h0 = __floats2bfloat162_rn(v.x, v.y);
    __nv_bfloat162 h1 = __floats2bfloat162_rn(v.z, v.w);
    __nv_bfloat162 l0 = __floats2bfloat162_rn(v.x - __bfloat162float(h0.x),
                                              v.y - __bfloat162float(h0.y));
    __nv_bfloat162 l1 = __floats2bfloat162_rn(v.z - __bfloat162float(h1.x),
                                              v.w - __bfloat162float(h1.y));
    hi.x = *(uint32_t*)&h0; hi.y = *(uint32_t*)&h1;
    lo.x = *(uint32_t*)&l0; lo.y = *(uint32_t*)&l1;
}

__device__ __forceinline__ void cvt_h(float4 v, uint2& hi) {
    __nv_bfloat162 h0 = __floats2bfloat162_rn(v.x, v.y);
    __nv_bfloat162 h1 = __floats2bfloat162_rn(v.z, v.w);
    hi.x = *(uint32_t*)&h0; hi.y = *(uint32_t*)&h1;
}

// ============ Gram kernel (proven R5): 128 thr, KC=16, K-split grid =========
__device__ __forceinline__ void gram_store_stage(char* bufp, const float4* rI,
                                                 const float4* rJ, int row, int c4) {
#pragma unroll
    for (int it = 0; it < 4; it++) {
        const int col4 = c4 + it * 8;
        const int chunk = col4 >> 1;
        const uint32_t off = (uint32_t)(row * 256) +
                             ((chunk ^ (row & 7)) << 4) + ((col4 & 1) * 8);
        uint2 hi, lo;
        cvt_hl(rI[it], hi, lo);
        *(uint2*)(bufp + off)         = hi;
        *(uint2*)(bufp + GREGB + off) = lo;
        cvt_hl(rJ[it], hi, lo);
        *(uint2*)(bufp + 2 * GREGB + off) = hi;
        *(uint2*)(bufp + 3 * GREGB + off) = lo;
    }
}

__device__ __forceinline__ void gram_compute(uint32_t u, float acc[4][8][4],
                                             int wm, int wn, int g, int tr) {
    const uint32_t IHI = u, ILO = u + GREGB, JHI = u + 2 * GREGB, JLO = u + 3 * GREGB;
    const int rowA = ((g & 2) ? 8 : 0) + tr;
    const int rowB = ((g & 1) ? 8 : 0) + tr;
    uint32_t ax[4][4], bh[4][4], bx[4][4];
#pragma unroll
    for (int mi = 0; mi < 4; mi++)
        ldsm4t(ax[mi], swz256(IHI, rowA, (wm >> 3) + mi * 2 + (g & 1)));
#pragma unroll
    for (int nb = 0; nb < 4; nb++)
        ldsm4t(bh[nb], swz256(JHI, rowB, (wn >> 3) + nb * 2 + (g >> 1)));
#pragma unroll
    for (int mi = 0; mi < 4; mi++)
#pragma unroll
        for (int nj = 0; nj < 8; nj++)
            mma16816(acc[mi][nj], ax[mi],
                     bh[nj >> 1][(nj & 1) * 2], bh[nj >> 1][(nj & 1) * 2 + 1]);
#pragma unroll
    for (int nb = 0; nb < 4; nb++)
        ldsm4t(bx[nb], swz256(JLO, rowB, (wn >> 3) + nb * 2 + (g >> 1)));
#pragma unroll
    for (int mi = 0; mi < 4; mi++)
#pragma unroll
        for (int nj = 0; nj < 8; nj++)
            mma16816(acc[mi][nj], ax[mi],
                     bx[nj >> 1][(nj & 1) * 2], bx[nj >> 1][(nj & 1) * 2 + 1]);
#pragma unroll
    for (int mi = 0; mi < 4; mi++)
        ldsm4t(ax[mi], swz256(ILO, rowA, (wm >> 3) + mi * 2 + (g & 1)));
#pragma unroll
    for (int mi = 0; mi < 4; mi++)
#pragma unroll
        for (int nj = 0; nj < 8; nj++)
            mma16816(acc[mi][nj], ax[mi],
                     bh[nj >> 1][(nj & 1) * 2], bh[nj >> 1][(nj & 1) * 2 + 1]);
}

__global__ void __launch_bounds__(128)
ata_mma_kernel(const float* __restrict__ a0, const float* __restrict__ a1,
               const float* __restrict__ a2, int Kper)
{
    extern __shared__ __align__(16) char dynsmem[];

    const int z = blockIdx.z;
    const float* A = (z == 0) ? a0 : ((z == 1) ? a1 : a2);
    float* C = g_part[blockIdx.y][z];

    int t = blockIdx.x, bi = 0;
    while (t >= 8 - bi) { t -= 8 - bi; bi++; }
    const int bj = bi + t;
    const int i0 = bi * 128, j0 = bj * 128;

    const int tid = threadIdx.x;
    const int w = tid >> 5, l = tid & 31;
    const int wm = (w >> 1) * 64, wn = (w & 1) * 64;
    const int tr = l & 7, g = l >> 3;
    const int row = tid >> 3, c4 = tid & 7;

    const uint32_t sb = smem_u32(dynsmem);
    const uint32_t ab = (sb + 1023u) & ~1023u;
    char* aptr = dynsmem + (ab - sb);

    float acc[4][8][4];
#pragma unroll
    for (int mi = 0; mi < 4; mi++)
#pragma unroll
        for (int nj = 0; nj < 8; nj++)
#pragma unroll
            for (int q = 0; q < 4; q++) acc[mi][nj][q] = 0.0f;

    const size_t kbase = (size_t)blockIdx.y * Kper;
    const float* pI = A + kbase * DIM + i0 + c4 * 4;
    const float* pJ = A + kbase * DIM + j0 + c4 * 4;

    const int S = Kper / KCG;
    float4 rI[4], rJ[4];
    {
        const size_t b0 = (size_t)row * DIM;
#pragma unroll
        for (int it = 0; it < 4; it++) {
            rI[it] = *(const float4*)(pI + b0 + it * 32);
            rJ[it] = *(const float4*)(pJ + b0 + it * 32);
        }
    }
    gram_store_stage(aptr, rI, rJ, row, c4);
    {
        const size_t b1 = (size_t)(KCG + row) * DIM;
#pragma unroll
        for (int it = 0; it < 4; it++) {
            rI[it] = *(const float4*)(pI + b1 + it * 32);
            rJ[it] = *(const float4*)(pJ + b1 + it * 32);
        }
    }
    __syncthreads();

    for (int s = 0; s < S; s++) {
        const int b = s & 1;
        if (s + 1 < S)
            gram_store_stage(aptr + (b ^ 1) * GSTAGEB, rI, rJ, row, c4);
        if (s + 2 < S) {
            const size_t bb = (size_t)((s + 2) * KCG + row) * DIM;
#pragma unroll
            for (int it = 0; it < 4; it++) {
                rI[it] = *(const float4*)(pI + bb + it * 32);
                rJ[it] = *(const float4*)(pJ + bb + it * 32);
            }
        }
        gram_compute(ab + b * GSTAGEB, acc, wm, wn, g, tr);
        __syncthreads();
    }

    const int r  = l >> 2;
    const int c2 = 2 * (l & 3);
#pragma unroll
    for (int mi = 0; mi < 4; mi++) {
#pragma unroll
        for (int nj = 0; nj < 8; nj++) {
            float* a = acc[mi][nj];
            const int gr = i0 + wm + mi * 16 + r;
            const int gc = j0 + wn + nj * 8 + c2;
            *(float2*)&C[(size_t)gr * DIM + gc]       = make_float2(a[0], a[1]);
            *(float2*)&C[(size_t)(gr + 8) * DIM + gc] = make_float2(a[2], a[3]);
            if (bi != bj) {
                C[(size_t)gc * DIM + gr]           = a[0];
                C[(size_t)(gc + 1) * DIM + gr]     = a[1];
                C[(size_t)gc * DIM + gr + 8]       = a[2];
                C[(size_t)(gc + 1) * DIM + gr + 8] = a[3];
            }
        }
    }
}

__global__ void add_parts_kernel() {
    const int z = blockIdx.y;
    float4* d        = reinterpret_cast<float4*>(g_bufA[z]);
    const float4* p0 = reinterpret_cast<const float4*>(g_part[0][z]);
    const float4* p1 = reinterpret_cast<const float4*>(g_part[1][z]);
    const float4* p2 = reinterpret_cast<const float4*>(g_part[2][z]);
    const float4* p3 = reinterpret_cast<const float4*>(g_part[3][z]);
    const int n = DIM * DIM / 4;
    for (int i = blockIdx.x * blockDim.x + threadIdx.x; i < n;
         i += gridDim.x * blockDim.x) {
        float4 a = p0[i], b = p1[i], c = p2[i], e = p3[i];
        float4 o;
        o.x = (a.x + b.x) + (c.x + e.x);
        o.y = (a.y + b.y) + (c.y + e.y);
        o.z = (a.z + b.z) + (c.z + e.z);
        o.w = (a.w + b.w) + (c.w + e.w);
        d[i] = o;
    }
}

// ===== Squaring kernel (proven R4, templated precision): 256 thr, 128x128 ===
template <int NP>
__device__ __forceinline__ void sq_store_stage(char* bufp, const float4* rI,
                                               const float4* rJ, int lrow, int l) {
    const int chunk = l >> 1;
    const int boff  = (l & 1) << 3;
#pragma unroll
    for (int rr = 0; rr < 4; rr++) {
        const int k = lrow + rr;
        const uint32_t off = (uint32_t)(k * 256) + ((chunk ^ (k & 7)) << 4) + boff;
        if (NP == 3) {
            uint2 hi, lo;
            cvt_hl(rI[rr], hi, lo);
            *(uint2*)(bufp + off)         = hi;
            *(uint2*)(bufp + SREGB + off) = lo;
            cvt_hl(rJ[rr], hi, lo);
            *(uint2*)(bufp + 2 * SREGB + off) = hi;
            *(uint2*)(bufp + 3 * SREGB + off) = lo;
        } else {
            uint2 hi;
            cvt_h(rI[rr], hi);
            *(uint2*)(bufp + off) = hi;
            cvt_h(rJ[rr], hi);
            *(uint2*)(bufp + 2 * SREGB + off) = hi;
        }
    }
}

template <int NP>
__device__ __forceinline__ void sq_compute_stage(uint32_t u, float acc[4][4][4],
                                                 int wm, int wn, int g, int tr) {
    const uint32_t IHI = u;
    const uint32_t ILO = u + SREGB;
    const uint32_t JHI = u + 2 * SREGB;
    const uint32_t JLO = u + 3 * SREGB;
#pragma unroll
    for (int kk = 0; kk < KCS; kk += 16) {
        uint32_t bh[2][4], bl[2][4], ah[4][4], al[4][4];
        const int rowB = kk + ((g & 1) ? 8 : 0) + tr;
#pragma unroll
        for (int nb = 0; nb < 2; nb++) {
            const int ch = (wn >> 3) + nb * 2 + (g >> 1);
            ldsm4t(bh[nb], swz256(JHI, rowB, ch));
            if (NP == 3) ldsm4t(bl[nb], swz256(JLO, rowB, ch));
        }
        const int rowA = kk + ((g & 2) ? 8 : 0) + tr;
#pragma unroll
        for (int mi = 0; mi < 4; mi++) {
            const int ch = (wm >> 3) + mi * 2 + (g & 1);
            ldsm4t(ah[mi], swz256(IHI, rowA, ch));
            if (NP == 3) ldsm4t(al[mi], swz256(ILO, rowA, ch));
        }
#pragma unroll
        for (int mi = 0; mi < 4; mi++)
#pragma unroll
            for (int nj = 0; nj < 4; nj++)
                mma16816(acc[mi][nj], ah[mi],
                         bh[nj >> 1][(nj & 1) * 2], bh[nj >> 1][(nj & 1) * 2 + 1]);
        if (NP == 3) {
#pragma unroll
            for (int mi = 0; mi < 4; mi++)
#pragma unroll
                for (int nj = 0; nj < 4; nj++)
                    mma16816(acc[mi][nj], ah[mi],
                             bl[nj >> 1][(nj & 1) * 2], bl[nj >> 1][(nj & 1) * 2 + 1]);
#pragma unroll
            for (int mi = 0; mi < 4; mi++)
#pragma unroll
                for (int nj = 0; nj < 4; nj++)
                    mma16816(acc[mi][nj], al[mi],
                             bh[nj >> 1][(nj & 1) * 2], bh[nj >> 1][(nj & 1) * 2 + 1]);
        }
    }
}

template <int NP>
__global__ void __launch_bounds__(256, 1)
sq_mma_kernel(int src_sel, int dst_sel, int do_write, double wfin)
{
    extern __shared__ __align__(16) char dynsmem[];
    __shared__ float sh_wsum[8];

    const int z = blockIdx.z;
    const float* A = (src_sel == 1) ? g_bufA[z] : g_bufB[z];
    float* C       = (dst_sel == 1) ? g_bufA[z] : g_bufB[z];

    int t = blockIdx.x, bi = 0;
    while (t >= 8 - bi) { t -= 8 - bi; bi++; }
    const int bj = bi + t;
    const int i0 = bi * 128, j0 = bj * 128;

    const int tid = threadIdx.x;
    const int w = tid >> 5, l = tid & 31;
    const int wm = (w >> 2) * 64;
    const int wn = (w & 3) * 32;
    const int tr = l & 7, g = l >> 3;

    const float sv = g_inv[z];
    const float s2 = sv * sv;

    const uint32_t sb = smem_u32(dynsmem);
    const uint32_t ab = (sb + 1023u) & ~1023u;
    char* aptr = dynsmem + (ab - sb);

    float acc[4][4][4];
#pragma unroll
    for (int mi = 0; mi < 4; mi++)
#pragma unroll
        for (int nj = 0; nj < 4; nj++)
#pragma unroll
            for (int q = 0; q < 4; q++) acc[mi][nj][q] = 0.0f;

    const float* AI = A + i0 + 4 * l;
    const float* AJ = A + j0 + 4 * l;
    const int lrow = w * 4;

    const int S = DIM / KCS;
    float4 rI[4], rJ[4];

#pragma unroll
    for (int rr = 0; rr < 4; rr++) {
        rI[rr] = *(const float4*)(AI + (size_t)(lrow + rr) * DIM);
        rJ[rr] = *(const float4*)(AJ + (size_t)(lrow + rr) * DIM);
    }
    sq_store_stage<NP>(aptr, rI, rJ, lrow, l);
#pragma unroll
    for (int rr = 0; rr < 4; rr++) {
        rI[rr] = *(const float4*)(AI + (size_t)(KCS + lrow + rr) * DIM);
        rJ[rr] = *(const float4*)(AJ + (size_t)(KCS + lrow + rr) * DIM);
    }
    __syncthreads();

    for (int s = 0; s < S; s++) {
        const int b = s & 1;
        if (s + 1 < S)
            sq_store_stage<NP>(aptr + (b ^ 1) * SSTAGEB, rI, rJ, lrow, l);
        if (s + 2 < S) {
            const int kn = (s + 2) * KCS;
#pragma unroll
            for (int rr = 0; rr < 4; rr++) {
                rI[rr] = *(const float4*)(AI + (size_t)(kn + lrow + rr) * DIM);
                rJ[rr] = *(const float4*)(AJ + (size_t)(kn + lrow + rr) * DIM);
            }
        }
        sq_compute_stage<NP>(ab + b * SSTAGEB, acc, wm, wn, g, tr);
        __syncthreads();
    }

    // ---- epilogue: scale, frobenius, store (+mirror) ----
    const float w2 = (bi == bj) ? 1.0f : 2.0f;
    float fr = 0.0f;
    const int r  = l >> 2;
    const int c2 = 2 * (l & 3);
#pragma unroll
    for (int mi = 0; mi < 4; mi++) {
#pragma unroll
        for (int nj = 0; nj < 4; nj++) {
            float* a = acc[mi][nj];
#pragma unroll
            for (int q = 0; q < 4; q++) {
                a[q] *= s2;
                fr = fmaf(w2 * a[q], a[q], fr);
            }
            if (do_write) {
                const int gr = i0 + wm + mi * 16 + r;
                const int gc = j0 + wn + nj * 8 + c2;
                *(float2*)&C[(size_t)gr * DIM + gc]       = make_float2(a[0], a[1]);
                *(float2*)&C[(size_t)(gr + 8) * DIM + gc] = make_float2(a[2], a[3]);
                if (bi != bj) {
                    C[(size_t)gc * DIM + gr]           = a[0];
                    C[(size_t)(gc + 1) * DIM + gr]     = a[1];
                    C[(size_t)gc * DIM + gr + 8]       = a[2];
                    C[(size_t)(gc + 1) * DIM + gr + 8] = a[3];
                }
            }
        }
    }

#pragma unroll
    for (int o = 16; o > 0; o >>= 1)
        fr += __shfl_xor_sync(0xffffffffu, fr, o);
    if (l == 0) sh_wsum[w] = fr;
    __syncthreads();
    if (tid == 0) {
        double tot = 0.0;
        for (int i = 0; i < 8; i++) tot += (double)sh_wsum[i];
        atomicAdd(&g_frob[z], tot);
        __threadfence();
        int tk = atomicAdd(&g_ctr[z], 1);
        if (tk == NTILE - 1) {
            g_ctr[z] = 0;
            __threadfence();
            double c = sqrt(g_frob[z]);
            g_inv[z] = (float)(1.0 / c);
            g_logacc[z] += log2(c) * wfin;
            g_frob[z] = 0.0;
        }
    }
}

__global__ void out_kernel(float* __restrict__ out) {
    double l0 = exp2(g_logacc[0]);
    double l1 = exp2(g_logacc[1]);
    double l2 = exp2(g_logacc[2]);
    out[0] = (float)(l0 + 0.5 * (l1 + l2));
}

extern "C" void kernel_launch(void* const* d_in, const int* in_sizes, int n_in,
                              void* d_out, int out_size)
{
    const float* f1 = (const float*)d_in[0];
    const float* f2 = (const float*)d_in[1];
    const float* f3 = (const float*)d_in[2];
    (void)in_sizes; (void)n_in; (void)out_size;

    static int configured = 0;
    if (!configured) {
        cudaFuncSetAttribute(ata_mma_kernel,
                             cudaFuncAttributeMaxDynamicSharedMemorySize, GSMEMB);
        cudaFuncSetAttribute(sq_mma_kernel<3>,
                             cudaFuncAttributeMaxDynamicSharedMemorySize, SSMEMB);
        cudaFuncSetAttribute(sq_mma_kernel<1>,
                             cudaFuncAttributeMaxDynamicSharedMemorySize, SSMEMB);
        configured = 1;
    }

    init_kernel<<<1, 4>>>();

    // Gram: 4-way K-split into partials, sum into bufA
    ata_mma_kernel<<<dim3(NTILE, KSPLIT, 3), 128, GSMEMB>>>(
        f1, f2, f3, NROWS / KSPLIT);
    add_parts_kernel<<<dim3(128, 3), 256>>>();

    int cur = 1;
    for (int k = 1; k <= M_SQ; k++) {
        int dst = 3 - cur;
        int dow = (k < M_SQ) ? 1 : 0;
        double wfin = exp2(-(double)k);
        if (k <= 2)
            sq_mma_kernel<3><<<dim3(NTILE, 1, 3), 256, SSMEMB>>>(cur, dst, dow, wfin);
        else
            sq_mma_kernel<1><<<dim3(NTILE, 1, 3), 256, SSMEMB>>>(cur, dst, dow, wfin);
        cur = dst;
    }
    out_kernel<<<1, 1>>>((float*)d_out);
}

// round 10
// speedup vs baseline: 1.6917x; 1.1898x over previous
#include <cuda_runtime.h>
#include <cuda_bf16.h>
#include <math.h>
#include <stdint.h>

// ---------------------------------------------------------------------------
// BSPLoss: out = lam1 + 0.5*(lam2+lam3), lam_i = top eigenvalue of F_i^T F_i.
// Gram (4-way K-split) + 10 Frobenius-normalized symmetric squarings.
// ALL GEMMs single-product bf16 (fp32 accum): empirically the bf16 rounding
// noise averages out (uT E u), total error ~2-5e-5 << 1e-3.
// First squaring fuses the Gram partial-sum into its loader.
// ---------------------------------------------------------------------------

#define DIM    1024
#define NROWS  8192
#define M_SQ   10
#define NTILE  36
#define KSPLIT 4
#define PSTR   ((size_t)3 * DIM * DIM)   // stride between g_part[k] planes (floats)

// Gram kernel (KC=16, 128 threads)
#define KCG     16
#define GREGB   4096                 // 16 rows * 256B
#define GSTAGEB (2 * GREGB)          // IHI | JHI = 8 KB
#define GSMEMB  (2 * GSTAGEB + 1024)

// Squaring kernel (KC=32, 256 threads, tile 128x128, warps 64x32)
#define KCS     32
#define SREGB   (KCS * 256)          // 8 KB
#define SSTAGEB (2 * SREGB)          // IHI | JHI = 16 KB
#define SSMEMB  (2 * SSTAGEB + 1024)

__device__ __align__(16) float g_bufA[3][DIM * DIM];
__device__ __align__(16) float g_bufB[3][DIM * DIM];
__device__ __align__(16) float g_part[KSPLIT][3][DIM * DIM];
__device__ double g_frob[3];
__device__ float  g_inv[3];
__device__ double g_logacc[3];
__device__ int    g_ctr[3];

__global__ void init_kernel() {
    int i = threadIdx.x;
    if (i < 3) { g_frob[i] = 0.0; g_inv[i] = 1.0f; g_logacc[i] = 0.0; g_ctr[i] = 0; }
}

__device__ __forceinline__ uint32_t smem_u32(const void* p) {
    uint32_t a;
    asm("{ .reg .u64 t; cvta.to.shared.u64 t, %1; cvt.u32.u64 %0, t; }"
        : "=r"(a) : "l"(p));
    return a;
}

__device__ __forceinline__ void ldsm4t(uint32_t* r, uint32_t addr) {
    asm volatile("ldmatrix.sync.aligned.m8n8.x4.trans.shared.b16 {%0,%1,%2,%3}, [%4];"
                 : "=r"(r[0]), "=r"(r[1]), "=r"(r[2]), "=r"(r[3]) : "r"(addr));
}

__device__ __forceinline__ void mma16816(float* c, const uint32_t* a,
                                         uint32_t b0, uint32_t b1) {
    asm volatile("mma.sync.aligned.m16n8k16.row.col.f32.bf16.bf16.f32 "
                 "{%0,%1,%2,%3}, {%4,%5,%6,%7}, {%8,%9}, {%0,%1,%2,%3};"
                 : "+f"(c[0]), "+f"(c[1]), "+f"(c[2]), "+f"(c[3])
                 : "r"(a[0]), "r"(a[1]), "r"(a[2]), "r"(a[3]), "r"(b0), "r"(b1));
}

__device__ __forceinline__ uint32_t swz256(uint32_t base, int row, int chunk) {
    return base + row * 256 + ((chunk ^ (row & 7)) << 4);
}

__device__ __forceinline__ void cvt_h(float4 v, uint2& hi) {
    __nv_bfloat162 h0 = __floats2bfloat162_rn(v.x, v.y);
    __nv_bfloat162 h1 = __floats2bfloat162_rn(v.z, v.w);
    hi.x = *(uint32_t*)&h0; hi.y = *(uint32_t*)&h1;
}

// Load one float4, optionally summing the 4 Gram partial planes.
__device__ __forceinline__ float4 ldp(const float* p, int fused) {
    float4 v = *(const float4*)p;
    if (fused) {
        float4 w1 = *(const float4*)(p + PSTR);
        float4 w2 = *(const float4*)(p + 2 * PSTR);
        float4 w3 = *(const float4*)(p + 3 * PSTR);
        v.x = (v.x + w1.x) + (w2.x + w3.x);
        v.y = (v.y + w1.y) + (w2.y + w3.y);
        v.z = (v.z + w1.z) + (w2.z + w3.z);
        v.w = (v.w + w1.w) + (w2.w + w3.w);
    }
    return v;
}

// ============ Gram kernel: 128 thr, KC=16, K-split grid, single bf16 ========
__device__ __forceinline__ void gram_store_stage(char* bufp, const float4* rI,
                                                 const float4* rJ, int row, int c4) {
#pragma unroll
    for (int it = 0; it < 4; it++) {
        const int col4 = c4 + it * 8;
        const int chunk = col4 >> 1;
        const uint32_t off = (uint32_t)(row * 256) +
                             ((chunk ^ (row & 7)) << 4) + ((col4 & 1) * 8);
        uint2 hi;
        cvt_h(rI[it], hi);
        *(uint2*)(bufp + off) = hi;
        cvt_h(rJ[it], hi);
        *(uint2*)(bufp + GREGB + off) = hi;
    }
}

__device__ __forceinline__ void gram_compute(uint32_t u, float acc[4][8][4],
                                             int wm, int wn, int g, int tr) {
    const uint32_t IHI = u, JHI = u + GREGB;
    const int rowA = ((g & 2) ? 8 : 0) + tr;
    const int rowB = ((g & 1) ? 8 : 0) + tr;
    uint32_t ax[4][4], bh[4][4];
#pragma unroll
    for (int mi = 0; mi < 4; mi++)
        ldsm4t(ax[mi], swz256(IHI, rowA, (wm >> 3) + mi * 2 + (g & 1)));
#pragma unroll
    for (int nb = 0; nb < 4; nb++)
        ldsm4t(bh[nb], swz256(JHI, rowB, (wn >> 3) + nb * 2 + (g >> 1)));
#pragma unroll
    for (int mi = 0; mi < 4; mi++)
#pragma unroll
        for (int nj = 0; nj < 8; nj++)
            mma16816(acc[mi][nj], ax[mi],
                     bh[nj >> 1][(nj & 1) * 2], bh[nj >> 1][(nj & 1) * 2 + 1]);
}

__global__ void __launch_bounds__(128)
ata_mma_kernel(const float* __restrict__ a0, const float* __restrict__ a1,
               const float* __restrict__ a2, int Kper)
{
    extern __shared__ __align__(16) char dynsmem[];

    const int z = blockIdx.z;
    const float* A = (z == 0) ? a0 : ((z == 1) ? a1 : a2);
    float* C = g_part[blockIdx.y][z];

    int t = blockIdx.x, bi = 0;
    while (t >= 8 - bi) { t -= 8 - bi; bi++; }
    const int bj = bi + t;
    const int i0 = bi * 128, j0 = bj * 128;

    const int tid = threadIdx.x;
    const int w = tid >> 5, l = tid & 31;
    const int wm = (w >> 1) * 64, wn = (w & 1) * 64;
    const int tr = l & 7, g = l >> 3;
    const int row = tid >> 3, c4 = tid & 7;

    const uint32_t sb = smem_u32(dynsmem);
    const uint32_t ab = (sb + 1023u) & ~1023u;
    char* aptr = dynsmem + (ab - sb);

    float acc[4][8][4];
#pragma unroll
    for (int mi = 0; mi < 4; mi++)
#pragma unroll
        for (int nj = 0; nj < 8; nj++)
#pragma unroll
            for (int q = 0; q < 4; q++) acc[mi][nj][q] = 0.0f;

    const size_t kbase = (size_t)blockIdx.y * Kper;
    const float* pI = A + kbase * DIM + i0 + c4 * 4;
    const float* pJ = A + kbase * DIM + j0 + c4 * 4;

    const int S = Kper / KCG;
    float4 rI[4], rJ[4];
    {
        const size_t b0 = (size_t)row * DIM;
#pragma unroll
        for (int it = 0; it < 4; it++) {
            rI[it] = *(const float4*)(pI + b0 + it * 32);
            rJ[it] = *(const float4*)(pJ + b0 + it * 32);
        }
    }
    gram_store_stage(aptr, rI, rJ, row, c4);
    {
        const size_t b1 = (size_t)(KCG + row) * DIM;
#pragma unroll
        for (int it = 0; it < 4; it++) {
            rI[it] = *(const float4*)(pI + b1 + it * 32);
            rJ[it] = *(const float4*)(pJ + b1 + it * 32);
        }
    }
    __syncthreads();

    for (int s = 0; s < S; s++) {
        const int b = s & 1;
        if (s + 1 < S)
            gram_store_stage(aptr + (b ^ 1) * GSTAGEB, rI, rJ, row, c4);
        if (s + 2 < S) {
            const size_t bb = (size_t)((s + 2) * KCG + row) * DIM;
#pragma unroll
            for (int it = 0; it < 4; it++) {
                rI[it] = *(const float4*)(pI + bb + it * 32);
                rJ[it] = *(const float4*)(pJ + bb + it * 32);
            }
        }
        gram_compute(ab + b * GSTAGEB, acc, wm, wn, g, tr);
        __syncthreads();
    }

    const int r  = l >> 2;
    const int c2 = 2 * (l & 3);
#pragma unroll
    for (int mi = 0; mi < 4; mi++) {
#pragma unroll
        for (int nj = 0; nj < 8; nj++) {
            float* a = acc[mi][nj];
            const int gr = i0 + wm + mi * 16 + r;
            const int gc = j0 + wn + nj * 8 + c2;
            *(float2*)&C[(size_t)gr * DIM + gc]       = make_float2(a[0], a[1]);
            *(float2*)&C[(size_t)(gr + 8) * DIM + gc] = make_float2(a[2], a[3]);
            if (bi != bj) {
                C[(size_t)gc * DIM + gr]           = a[0];
                C[(size_t)(gc + 1) * DIM + gr]     = a[1];
                C[(size_t)gc * DIM + gr + 8]       = a[2];
                C[(size_t)(gc + 1) * DIM + gr + 8] = a[3];
            }
        }
    }
}

// ===== Squaring kernel: 256 thr, tile 128x128, warps 64x32, single bf16 =====
__device__ __forceinline__ void sq_store_stage(char* bufp, const float4* rI,
                                               const float4* rJ, int lrow, int l) {
    const int chunk = l >> 1;
    const int boff  = (l & 1) << 3;
#pragma unroll
    for (int rr = 0; rr < 4; rr++) {
        const int k = lrow + rr;
        const uint32_t off = (uint32_t)(k * 256) + ((chunk ^ (k & 7)) << 4) + boff;
        uint2 hi;
        cvt_h(rI[rr], hi);
        *(uint2*)(bufp + off) = hi;
        cvt_h(rJ[rr], hi);
        *(uint2*)(bufp + SREGB + off) = hi;
    }
}

__device__ __forceinline__ void sq_compute_stage(uint32_t u, float acc[4][4][4],
                                                 int wm, int wn, int g, int tr) {
    const uint32_t IHI = u;
    const uint32_t JHI = u + SREGB;
#pragma unroll
    for (int kk = 0; kk < KCS; kk += 16) {
        uint32_t bh[2][4], ah[4][4];
        const int rowB = kk + ((g & 1) ? 8 : 0) + tr;
#pragma unroll
        for (int nb = 0; nb < 2; nb++) {
            const int ch = (wn >> 3) + nb * 2 + (g >> 1);
            ldsm4t(bh[nb], swz256(JHI, rowB, ch));
        }
        const int rowA = kk + ((g & 2) ? 8 : 0) + tr;
#pragma unroll
        for (int mi = 0; mi < 4; mi++) {
            const int ch = (wm >> 3) + mi * 2 + (g & 1);
            ldsm4t(ah[mi], swz256(IHI, rowA, ch));
        }
#pragma unroll
        for (int mi = 0; mi < 4; mi++)
#pragma unroll
            for (int nj = 0; nj < 4; nj++)
                mma16816(acc[mi][nj], ah[mi],
                         bh[nj >> 1][(nj & 1) * 2], bh[nj >> 1][(nj & 1) * 2 + 1]);
    }
}

// src_sel: 1 bufA, 2 bufB, 3 fused sum of g_part[0..3].
__global__ void __launch_bounds__(256, 1)
sq_mma_kernel(int src_sel, int dst_sel, int do_write, double wfin)
{
    extern __shared__ __align__(16) char dynsmem[];
    __shared__ float sh_wsum[8];

    const int z = blockIdx.z;
    const float* A;
    int fused = 0;
    if (src_sel == 1)      A = g_bufA[z];
    else if (src_sel == 2) A = g_bufB[z];
    else                 { A = g_part[0][z]; fused = 1; }
    float* C = (dst_sel == 1) ? g_bufA[z] : g_bufB[z];

    int t = blockIdx.x, bi = 0;
    while (t >= 8 - bi) { t -= 8 - bi; bi++; }
    const int bj = bi + t;
    const int i0 = bi * 128, j0 = bj * 128;

    const int tid = threadIdx.x;
    const int w = tid >> 5, l = tid & 31;
    const int wm = (w >> 2) * 64;
    const int wn = (w & 3) * 32;
    const int tr = l & 7, g = l >> 3;

    const float sv = g_inv[z];
    const float s2 = sv * sv;

    const uint32_t sb = smem_u32(dynsmem);
    const uint32_t ab = (sb + 1023u) & ~1023u;
    char* aptr = dynsmem + (ab - sb);

    float acc[4][4][4];
#pragma unroll
    for (int mi = 0; mi < 4; mi++)
#pragma unroll
        for (int nj = 0; nj < 4; nj++)
#pragma unroll
            for (int q = 0; q < 4; q++) acc[mi][nj][q] = 0.0f;

    const float* AI = A + i0 + 4 * l;
    const float* AJ = A + j0 + 4 * l;
    const int lrow = w * 4;

    const int S = DIM / KCS;
    float4 rI[4], rJ[4];

#pragma unroll
    for (int rr = 0; rr < 4; rr++) {
        rI[rr] = ldp(AI + (size_t)(lrow + rr) * DIM, fused);
        rJ[rr] = ldp(AJ + (size_t)(lrow + rr) * DIM, fused);
    }
    sq_store_stage(aptr, rI, rJ, lrow, l);
#pragma unroll
    for (int rr = 0; rr < 4; rr++) {
        rI[rr] = ldp(AI + (size_t)(KCS + lrow + rr) * DIM, fused);
        rJ[rr] = ldp(AJ + (size_t)(KCS + lrow + rr) * DIM, fused);
    }
    __syncthreads();

    for (int s = 0; s < S; s++) {
        const int b = s & 1;
        if (s + 1 < S)
            sq_store_stage(aptr + (b ^ 1) * SSTAGEB, rI, rJ, lrow, l);
        if (s + 2 < S) {
            const int kn = (s + 2) * KCS;
#pragma unroll
            for (int rr = 0; rr < 4; rr++) {
                rI[rr] = ldp(AI + (size_t)(kn + lrow + rr) * DIM, fused);
                rJ[rr] = ldp(AJ + (size_t)(kn + lrow + rr) * DIM, fused);
            }
        }
        sq_compute_stage(ab + b * SSTAGEB, acc, wm, wn, g, tr);
        __syncthreads();
    }

    // ---- epilogue: scale, frobenius, store (+mirror) ----
    const float w2 = (bi == bj) ? 1.0f : 2.0f;
    float fr = 0.0f;
    const int r  = l >> 2;
    const int c2 = 2 * (l & 3);
#pragma unroll
    for (int mi = 0; mi < 4; mi++) {
#pragma unroll
        for (int nj = 0; nj < 4; nj++) {
            float* a = acc[mi][nj];
#pragma unroll
            for (int q = 0; q < 4; q++) {
                a[q] *= s2;
                fr = fmaf(w2 * a[q], a[q], fr);
            }
            if (do_write) {
                const int gr = i0 + wm + mi * 16 + r;
                const int gc = j0 + wn + nj * 8 + c2;
                *(float2*)&C[(size_t)gr * DIM + gc]       = make_float2(a[0], a[1]);
                *(float2*)&C[(size_t)(gr + 8) * DIM + gc] = make_float2(a[2], a[3]);
                if (bi != bj) {
                    C[(size_t)gc * DIM + gr]           = a[0];
                    C[(size_t)(gc + 1) * DIM + gr]     = a[1];
                    C[(size_t)gc * DIM + gr + 8]       = a[2];
                    C[(size_t)(gc + 1) * DIM + gr + 8] = a[3];
                }
            }
        }
    }

#pragma unroll
    for (int o = 16; o > 0; o >>= 1)
        fr += __shfl_xor_sync(0xffffffffu, fr, o);
    if (l == 0) sh_wsum[w] = fr;
    __syncthreads();
    if (tid == 0) {
        double tot = 0.0;
        for (int i = 0; i < 8; i++) tot += (double)sh_wsum[i];
        atomicAdd(&g_frob[z], tot);
        __threadfence();
        int tk = atomicAdd(&g_ctr[z], 1);
        if (tk == NTILE - 1) {
            g_ctr[z] = 0;
            __threadfence();
            double c = sqrt(g_frob[z]);
            g_inv[z] = (float)(1.0 / c);
            g_logacc[z] += log2(c) * wfin;
            g_frob[z] = 0.0;
        }
    }
}

__global__ void out_kernel(float* __restrict__ out) {
    double l0 = exp2(g_logacc[0]);
    double l1 = exp2(g_logacc[1]);
    double l2 = exp2(g_logacc[2]);
    out[0] = (float)(l0 + 0.5 * (l1 + l2));
}

extern "C" void kernel_launch(void* const* d_in, const int* in_sizes, int n_in,
                              void* d_out, int out_size)
{
    const float* f1 = (const float*)d_in[0];
    const float* f2 = (const float*)d_in[1];
    const float* f3 = (const float*)d_in[2];
    (void)in_sizes; (void)n_in; (void)out_size;

    static int configured = 0;
    if (!configured) {
        cudaFuncSetAttribute(ata_mma_kernel,
                             cudaFuncAttributeMaxDynamicSharedMemorySize, GSMEMB);
        cudaFuncSetAttribute(sq_mma_kernel,
                             cudaFuncAttributeMaxDynamicSharedMemorySize, SSMEMB);
        configured = 1;
    }

    init_kernel<<<1, 4>>>();

    // Gram: 4-way K-split into partial planes (single bf16 product)
    ata_mma_kernel<<<dim3(NTILE, KSPLIT, 3), 128, GSMEMB>>>(
        f1, f2, f3, NROWS / KSPLIT);

    // k=1 squaring reads the summed partials directly (fused add)
    sq_mma_kernel<<<dim3(NTILE, 1, 3), 256, SSMEMB>>>(3, 1, 1, exp2(-1.0));
    int cur = 1;
    for (int k = 2; k <= M_SQ; k++) {
        int dst = 3 - cur;
        int dow = (k < M_SQ) ? 1 : 0;
        sq_mma_kernel<<<dim3(NTILE, 1, 3), 256, SSMEMB>>>(
            cur, dst, dow, exp2(-(double)k));
        cur = dst;
    }
    out_kernel<<<1, 1>>>((float*)d_out);
}

// round 11
// speedup vs baseline: 1.9137x; 1.1313x over previous
#include <cuda_runtime.h>
#include <cuda_bf16.h>
#include <math.h>
#include <stdint.h>

// ---------------------------------------------------------------------------
// BSPLoss: out = lam1 + 0.5*(lam2+lam3), lam_i = top eigenvalue of F_i^T F_i.
// Gram (4-way K-split, fp32 partials) + 9 Frobenius-normalized symmetric
// squarings.  The squaring chain is carried in bf16: each epilogue stores
// bf16 directly (same rounding the next loader would have applied), halving
// load/store bytes and deleting all loader converts.  k=1 fuses the Gram
// partial-sum (fp32) into its loader.  All GEMMs: mma.sync bf16, fp32 accum.
// ---------------------------------------------------------------------------

#define DIM    1024
#define NROWS  8192
#define M_SQ   9
#define NTILE  36
#define KSPLIT 4
#define PSTR   ((size_t)3 * DIM * DIM)   // stride between g_part[k] planes

// Gram kernel (KC=16, 128 threads)
#define KCG     16
#define GREGB   4096
#define GSTAGEB (2 * GREGB)          // IHI | JHI = 8 KB
#define GSMEMB  (2 * GSTAGEB + 1024)

// Squaring kernel (KC=32, 256 threads, tile 128x128, warps 64x32)
#define KCS     32
#define SREGB   (KCS * 256)          // 8 KB
#define SSTAGEB (2 * SREGB)          // 16 KB
#define SSMEMB  (2 * SSTAGEB + 1024)

__device__ __align__(16) float          g_part[KSPLIT][3][DIM * DIM];
__device__ __align__(16) __nv_bfloat16  g_hbuf[2][3][DIM * DIM];
__device__ double g_frob[3];
__device__ float  g_inv[3];
__device__ double g_logacc[3];
__device__ int    g_ctr[3];

__global__ void init_kernel() {
    int i = threadIdx.x;
    if (i < 3) { g_frob[i] = 0.0; g_inv[i] = 1.0f; g_logacc[i] = 0.0; g_ctr[i] = 0; }
}

__device__ __forceinline__ uint32_t smem_u32(const void* p) {
    uint32_t a;
    asm("{ .reg .u64 t; cvta.to.shared.u64 t, %1; cvt.u32.u64 %0, t; }"
        : "=r"(a) : "l"(p));
    return a;
}

__device__ __forceinline__ void ldsm4t(uint32_t* r, uint32_t addr) {
    asm volatile("ldmatrix.sync.aligned.m8n8.x4.trans.shared.b16 {%0,%1,%2,%3}, [%4];"
                 : "=r"(r[0]), "=r"(r[1]), "=r"(r[2]), "=r"(r[3]) : "r"(addr));
}

__device__ __forceinline__ void mma16816(float* c, const uint32_t* a,
                                         uint32_t b0, uint32_t b1) {
    asm volatile("mma.sync.aligned.m16n8k16.row.col.f32.bf16.bf16.f32 "
                 "{%0,%1,%2,%3}, {%4,%5,%6,%7}, {%8,%9}, {%0,%1,%2,%3};"
                 : "+f"(c[0]), "+f"(c[1]), "+f"(c[2]), "+f"(c[3])
                 : "r"(a[0]), "r"(a[1]), "r"(a[2]), "r"(a[3]), "r"(b0), "r"(b1));
}

__device__ __forceinline__ uint32_t swz256(uint32_t base, int row, int chunk) {
    return base + row * 256 + ((chunk ^ (row & 7)) << 4);
}

__device__ __forceinline__ void cvt_h(float4 v, uint2& hi) {
    __nv_bfloat162 h0 = __floats2bfloat162_rn(v.x, v.y);
    __nv_bfloat162 h1 = __floats2bfloat162_rn(v.z, v.w);
    hi.x = *(uint32_t*)&h0; hi.y = *(uint32_t*)&h1;
}

// Load one float4, summing the 4 Gram partial planes.
__device__ __forceinline__ float4 ldp4(const float* p) {
    float4 v  = *(const float4*)p;
    float4 w1 = *(const float4*)(p + PSTR);
    float4 w2 = *(const float4*)(p + 2 * PSTR);
    float4 w3 = *(const float4*)(p + 3 * PSTR);
    v.x = (v.x + w1.x) + (w2.x + w3.x);
    v.y = (v.y + w1.y) + (w2.y + w3.y);
    v.z = (v.z + w1.z) + (w2.z + w3.z);
    v.w = (v.w + w1.w) + (w2.w + w3.w);
    return v;
}

// ============ Gram kernel: 128 thr, KC=16, K-split grid, single bf16 ========
__device__ __forceinline__ void gram_store_stage(char* bufp, const float4* rI,
                                                 const float4* rJ, int row, int c4) {
#pragma unroll
    for (int it = 0; it < 4; it++) {
        const int col4 = c4 + it * 8;
        const int chunk = col4 >> 1;
        const uint32_t off = (uint32_t)(row * 256) +
                             ((chunk ^ (row & 7)) << 4) + ((col4 & 1) * 8);
        uint2 hi;
        cvt_h(rI[it], hi);
        *(uint2*)(bufp + off) = hi;
        cvt_h(rJ[it], hi);
        *(uint2*)(bufp + GREGB + off) = hi;
    }
}

__device__ __forceinline__ void gram_compute(uint32_t u, float acc[4][8][4],
                                             int wm, int wn, int g, int tr) {
    const uint32_t IHI = u, JHI = u + GREGB;
    const int rowA = ((g & 2) ? 8 : 0) + tr;
    const int rowB = ((g & 1) ? 8 : 0) + tr;
    uint32_t ax[4][4], bh[4][4];
#pragma unroll
    for (int mi = 0; mi < 4; mi++)
        ldsm4t(ax[mi], swz256(IHI, rowA, (wm >> 3) + mi * 2 + (g & 1)));
#pragma unroll
    for (int nb = 0; nb < 4; nb++)
        ldsm4t(bh[nb], swz256(JHI, rowB, (wn >> 3) + nb * 2 + (g >> 1)));
#pragma unroll
    for (int mi = 0; mi < 4; mi++)
#pragma unroll
        for (int nj = 0; nj < 8; nj++)
            mma16816(acc[mi][nj], ax[mi],
                     bh[nj >> 1][(nj & 1) * 2], bh[nj >> 1][(nj & 1) * 2 + 1]);
}

__global__ void __launch_bounds__(128)
ata_mma_kernel(const float* __restrict__ a0, const float* __restrict__ a1,
               const float* __restrict__ a2, int Kper)
{
    extern __shared__ __align__(16) char dynsmem[];

    const int z = blockIdx.z;
    const float* A = (z == 0) ? a0 : ((z == 1) ? a1 : a2);
    float* C = g_part[blockIdx.y][z];

    int t = blockIdx.x, bi = 0;
    while (t >= 8 - bi) { t -= 8 - bi; bi++; }
    const int bj = bi + t;
    const int i0 = bi * 128, j0 = bj * 128;

    const int tid = threadIdx.x;
    const int w = tid >> 5, l = tid & 31;
    const int wm = (w >> 1) * 64, wn = (w & 1) * 64;
    const int tr = l & 7, g = l >> 3;
    const int row = tid >> 3, c4 = tid & 7;

    const uint32_t sb = smem_u32(dynsmem);
    const uint32_t ab = (sb + 1023u) & ~1023u;
    char* aptr = dynsmem + (ab - sb);

    float acc[4][8][4];
#pragma unroll
    for (int mi = 0; mi < 4; mi++)
#pragma unroll
        for (int nj = 0; nj < 8; nj++)
#pragma unroll
            for (int q = 0; q < 4; q++) acc[mi][nj][q] = 0.0f;

    const size_t kbase = (size_t)blockIdx.y * Kper;
    const float* pI = A + kbase * DIM + i0 + c4 * 4;
    const float* pJ = A + kbase * DIM + j0 + c4 * 4;

    const int S = Kper / KCG;
    float4 rI[4], rJ[4];
    {
        const size_t b0 = (size_t)row * DIM;
#pragma unroll
        for (int it = 0; it < 4; it++) {
            rI[it] = *(const float4*)(pI + b0 + it * 32);
            rJ[it] = *(const float4*)(pJ + b0 + it * 32);
        }
    }
    gram_store_stage(aptr, rI, rJ, row, c4);
    {
        const size_t b1 = (size_t)(KCG + row) * DIM;
#pragma unroll
        for (int it = 0; it < 4; it++) {
            rI[it] = *(const float4*)(pI + b1 + it * 32);
            rJ[it] = *(const float4*)(pJ + b1 + it * 32);
        }
    }
    __syncthreads();

    for (int s = 0; s < S; s++) {
        const int b = s & 1;
        if (s + 1 < S)
            gram_store_stage(aptr + (b ^ 1) * GSTAGEB, rI, rJ, row, c4);
        if (s + 2 < S) {
            const size_t bb = (size_t)((s + 2) * KCG + row) * DIM;
#pragma unroll
            for (int it = 0; it < 4; it++) {
                rI[it] = *(const float4*)(pI + bb + it * 32);
                rJ[it] = *(const float4*)(pJ + bb + it * 32);
            }
        }
        gram_compute(ab + b * GSTAGEB, acc, wm, wn, g, tr);
        __syncthreads();
    }

    const int r  = l >> 2;
    const int c2 = 2 * (l & 3);
#pragma unroll
    for (int mi = 0; mi < 4; mi++) {
#pragma unroll
        for (int nj = 0; nj < 8; nj++) {
            float* a = acc[mi][nj];
            const int gr = i0 + wm + mi * 16 + r;
            const int gc = j0 + wn + nj * 8 + c2;
            *(float2*)&C[(size_t)gr * DIM + gc]       = make_float2(a[0], a[1]);
            *(float2*)&C[(size_t)(gr + 8) * DIM + gc] = make_float2(a[2], a[3]);
            if (bi != bj) {
                C[(size_t)gc * DIM + gr]           = a[0];
                C[(size_t)(gc + 1) * DIM + gr]     = a[1];
                C[(size_t)gc * DIM + gr + 8]       = a[2];
                C[(size_t)(gc + 1) * DIM + gr + 8] = a[3];
            }
        }
    }
}

// ===== Squaring kernel: 256 thr, tile 128x128, warps 64x32, bf16 chain ======
__device__ __forceinline__ void sq_load(const float* AIf, const float* AJf,
                                        const __nv_bfloat16* AIb,
                                        const __nv_bfloat16* AJb,
                                        int fused, int kbase, int lrow,
                                        uint2* sI, uint2* sJ) {
    if (fused) {
#pragma unroll
        for (int rr = 0; rr < 4; rr++) {
            float4 v = ldp4(AIf + (size_t)(kbase + lrow + rr) * DIM);
            cvt_h(v, sI[rr]);
            v = ldp4(AJf + (size_t)(kbase + lrow + rr) * DIM);
            cvt_h(v, sJ[rr]);
        }
    } else {
#pragma unroll
        for (int rr = 0; rr < 4; rr++) {
            sI[rr] = *(const uint2*)(AIb + (size_t)(kbase + lrow + rr) * DIM);
            sJ[rr] = *(const uint2*)(AJb + (size_t)(kbase + lrow + rr) * DIM);
        }
    }
}

__device__ __forceinline__ void sq_store(char* bufp, const uint2* sI,
                                         const uint2* sJ, int lrow, int l) {
    const int chunk = l >> 1;
    const int boff  = (l & 1) << 3;
#pragma unroll
    for (int rr = 0; rr < 4; rr++) {
        const int k = lrow + rr;
        const uint32_t off = (uint32_t)(k * 256) + ((chunk ^ (k & 7)) << 4) + boff;
        *(uint2*)(bufp + off)         = sI[rr];
        *(uint2*)(bufp + SREGB + off) = sJ[rr];
    }
}

__device__ __forceinline__ void sq_compute_stage(uint32_t u, float acc[4][4][4],
                                                 int wm, int wn, int g, int tr) {
    const uint32_t IHI = u;
    const uint32_t JHI = u + SREGB;
#pragma unroll
    for (int kk = 0; kk < KCS; kk += 16) {
        uint32_t bh[2][4], ah[4][4];
        const int rowB = kk + ((g & 1) ? 8 : 0) + tr;
#pragma unroll
        for (int nb = 0; nb < 2; nb++) {
            const int ch = (wn >> 3) + nb * 2 + (g >> 1);
            ldsm4t(bh[nb], swz256(JHI, rowB, ch));
        }
        const int rowA = kk + ((g & 2) ? 8 : 0) + tr;
#pragma unroll
        for (int mi = 0; mi < 4; mi++) {
            const int ch = (wm >> 3) + mi * 2 + (g & 1);
            ldsm4t(ah[mi], swz256(IHI, rowA, ch));
        }
#pragma unroll
        for (int mi = 0; mi < 4; mi++)
#pragma unroll
            for (int nj = 0; nj < 4; nj++)
                mma16816(acc[mi][nj], ah[mi],
                         bh[nj >> 1][(nj & 1) * 2], bh[nj >> 1][(nj & 1) * 2 + 1]);
    }
}

// src_sel: 3 = fused fp32 partial planes; 0/1 = g_hbuf index.  dst_sel: 0/1.
__global__ void __launch_bounds__(256, 1)
sq_mma_kernel(int src_sel, int dst_sel, int do_write, double wfin)
{
    extern __shared__ __align__(16) char dynsmem[];
    __shared__ float sh_wsum[8];

    const int z = blockIdx.z;
    const int fused = (src_sel == 3);
    const float* Af = g_part[0][z];
    const __nv_bfloat16* Ab = fused ? g_hbuf[0][z] : g_hbuf[src_sel][z];
    __nv_bfloat16* Cb = g_hbuf[dst_sel][z];

    int t = blockIdx.x, bi = 0;
    while (t >= 8 - bi) { t -= 8 - bi; bi++; }
    const int bj = bi + t;
    const int i0 = bi * 128, j0 = bj * 128;

    const int tid = threadIdx.x;
    const int w = tid >> 5, l = tid & 31;
    const int wm = (w >> 2) * 64;
    const int wn = (w & 3) * 32;
    const int tr = l & 7, g = l >> 3;

    const float sv = g_inv[z];
    const float s2 = sv * sv;

    const uint32_t sb = smem_u32(dynsmem);
    const uint32_t ab = (sb + 1023u) & ~1023u;
    char* aptr = dynsmem + (ab - sb);

    float acc[4][4][4];
#pragma unroll
    for (int mi = 0; mi < 4; mi++)
#pragma unroll
        for (int nj = 0; nj < 4; nj++)
#pragma unroll
            for (int q = 0; q < 4; q++) acc[mi][nj][q] = 0.0f;

    const float* AIf = Af + i0 + 4 * l;
    const float* AJf = Af + j0 + 4 * l;
    const __nv_bfloat16* AIb = Ab + i0 + 4 * l;
    const __nv_bfloat16* AJb = Ab + j0 + 4 * l;
    const int lrow = w * 4;

    const int S = DIM / KCS;
    uint2 sI[4], sJ[4];

    sq_load(AIf, AJf, AIb, AJb, fused, 0, lrow, sI, sJ);
    sq_store(aptr, sI, sJ, lrow, l);
    sq_load(AIf, AJf, AIb, AJb, fused, KCS, lrow, sI, sJ);
    __syncthreads();

    for (int s = 0; s < S; s++) {
        const int b = s & 1;
        if (s + 1 < S)
            sq_store(aptr + (b ^ 1) * SSTAGEB, sI, sJ, lrow, l);
        if (s + 2 < S)
            sq_load(AIf, AJf, AIb, AJb, fused, (s + 2) * KCS, lrow, sI, sJ);
        sq_compute_stage(ab + b * SSTAGEB, acc, wm, wn, g, tr);
        __syncthreads();
    }

    // ---- epilogue: scale, frobenius, bf16 store (+mirror) ----
    const float w2 = (bi == bj) ? 1.0f : 2.0f;
    float fr = 0.0f;
    const int r  = l >> 2;
    const int c2 = 2 * (l & 3);
#pragma unroll
    for (int mi = 0; mi < 4; mi++) {
#pragma unroll
        for (int nj = 0; nj < 4; nj++) {
            float* a = acc[mi][nj];
#pragma unroll
            for (int q = 0; q < 4; q++) {
                a[q] *= s2;
                fr = fmaf(w2 * a[q], a[q], fr);
            }
            if (do_write) {
                const int gr = i0 + wm + mi * 16 + r;
                const int gc = j0 + wn + nj * 8 + c2;
                __nv_bfloat162 h01 = __floats2bfloat162_rn(a[0], a[1]);
                __nv_bfloat162 h23 = __floats2bfloat162_rn(a[2], a[3]);
                *reinterpret_cast<__nv_bfloat162*>(&Cb[(size_t)gr * DIM + gc]) = h01;
                *reinterpret_cast<__nv_bfloat162*>(&Cb[(size_t)(gr + 8) * DIM + gc]) = h23;
                if (bi != bj) {
                    Cb[(size_t)gc * DIM + gr]           = h01.x;
                    Cb[(size_t)(gc + 1) * DIM + gr]     = h01.y;
                    Cb[(size_t)gc * DIM + gr + 8]       = h23.x;
                    Cb[(size_t)(gc + 1) * DIM + gr + 8] = h23.y;
                }
            }
        }
    }

#pragma unroll
    for (int o = 16; o > 0; o >>= 1)
        fr += __shfl_xor_sync(0xffffffffu, fr, o);
    if (l == 0) sh_wsum[w] = fr;
    __syncthreads();
    if (tid == 0) {
        double tot = 0.0;
        for (int i = 0; i < 8; i++) tot += (double)sh_wsum[i];
        atomicAdd(&g_frob[z], tot);
        __threadfence();
        int tk = atomicAdd(&g_ctr[z], 1);
        if (tk == NTILE - 1) {
            g_ctr[z] = 0;
            __threadfence();
            double c = sqrt(g_frob[z]);
            g_inv[z] = (float)(1.0 / c);
            g_logacc[z] += log2(c) * wfin;
            g_frob[z] = 0.0;
        }
    }
}

__global__ void out_kernel(float* __restrict__ out) {
    double l0 = exp2(g_logacc[0]);
    double l1 = exp2(g_logacc[1]);
    double l2 = exp2(g_logacc[2]);
    out[0] = (float)(l0 + 0.5 * (l1 + l2));
}

extern "C" void kernel_launch(void* const* d_in, const int* in_sizes, int n_in,
                              void* d_out, int out_size)
{
    const float* f1 = (const float*)d_in[0];
    const float* f2 = (const float*)d_in[1];
    const float* f3 = (const float*)d_in[2];
    (void)in_sizes; (void)n_in; (void)out_size;

    static int configured = 0;
    if (!configured) {
        cudaFuncSetAttribute(ata_mma_kernel,
                             cudaFuncAttributeMaxDynamicSharedMemorySize, GSMEMB);
        cudaFuncSetAttribute(sq_mma_kernel,
                             cudaFuncAttributeMaxDynamicSharedMemorySize, SSMEMB);
        configured = 1;
    }

    init_kernel<<<1, 4>>>();

    // Gram: 4-way K-split into fp32 partial planes (single bf16 product)
    ata_mma_kernel<<<dim3(NTILE, KSPLIT, 3), 128, GSMEMB>>>(
        f1, f2, f3, NROWS / KSPLIT);

    // k=1: fused partial-sum loader (fp32), writes bf16 -> hbuf[0]
    sq_mma_kernel<<<dim3(NTILE, 1, 3), 256, SSMEMB>>>(3, 0, 1, exp2(-1.0));
    int cur = 0;
    for (int k = 2; k <= M_SQ; k++) {
        int dst = 1 - cur;
        int dow = (k < M_SQ) ? 1 : 0;
        sq_mma_kernel<<<dim3(NTILE, 1, 3), 256, SSMEMB>>>(
            cur, dst, dow, exp2(-(double)k));
        cur = dst;
    }
    out_kernel<<<1, 1>>>((float*)d_out);
}